// round 1
// baseline (speedup 1.0000x reference)
#include <cuda_runtime.h>
#include <cstdint>

// ---------------- problem constants ----------------
#define B_    4
#define C_    64
#define HW_   32
#define NPIX  1024            // 32*32
#define PR    34              // padded rows actually used (0..33)
#define PSTR  36              // padded row stride (bank-friendly)
#define PLANE (PR * PSTR)     // 1224 floats per (b,c) plane
#define S_    8               // K-split factor
#define CCHUNK 8              // channels per split
#define KBLK  (CCHUNK * 9)    // 72 k-steps per block

// ---------------- scratch (device globals; no allocation allowed) -------
__device__ float g_a1[B_ * C_ * PLANE];          // relu(bn1(x)), zero-padded
__device__ float g_a2[B_ * C_ * PLANE];          // relu(bn2(adder1)), zero-padded
__device__ float g_p1[S_ * B_ * C_ * NPIX];      // adder1 split partials
__device__ float g_p2[S_ * B_ * C_ * NPIX];      // adder2 split partials
__device__ float g_out2[B_ * C_ * NPIX];         // adder2 full output
__device__ float g_s[B_ * C_];                   // channel means
__device__ float g_g[B_ * C_];                   // SE gate

// packed fp32x2 add (Blackwell)
__device__ __forceinline__ unsigned long long f2add(unsigned long long a,
                                                    unsigned long long b) {
    unsigned long long r;
    asm("add.rn.f32x2 %0, %1, %2;" : "=l"(r) : "l"(a), "l"(b));
    return r;
}

// ---------------- BN + ReLU into zero-padded layout ----------------
// stage==0: input = x (d_in), output = g_a1
// stage==1: input = sum over S_ partials of g_p1, output = g_a2
__global__ void k_bnpad(const float* __restrict__ xin, int stage,
                        const float* __restrict__ gam,
                        const float* __restrict__ bet,
                        const float* __restrict__ mu,
                        const float* __restrict__ var) {
    int idx = blockIdx.x * blockDim.x + threadIdx.x;
    const int total = B_ * C_ * PLANE;
    if (idx >= total) return;
    float* outp = stage ? g_a2 : g_a1;

    int q  = idx % PSTR;
    int t  = idx / PSTR;
    int r  = t % PR;
    int bc = t / PR;

    float val = 0.f;
    if (r >= 1 && r <= 32 && q >= 1 && q <= 32) {
        int pix = bc * NPIX + (r - 1) * 32 + (q - 1);
        float s;
        if (stage) {
            s = 0.f;
#pragma unroll
            for (int sp = 0; sp < S_; sp++)
                s += g_p1[sp * (B_ * C_ * NPIX) + pix];
        } else {
            s = xin[pix];
        }
        int c = bc & (C_ - 1);
        float inv = gam[c] * rsqrtf(var[c] + 1e-5f);
        float o = s * inv + (bet[c] - mu[c] * inv);
        val = fmaxf(o, 0.f);
    }
    outp[idx] = val;
}

// ---------------- AdderNet conv, K-split, packed f32x2 ----------------
// grid: (32 pixel-tiles, 8 k-splits); block: 128 threads
// pixel tile = one batch image's 4 rows x 32 cols (128 px) x all 64 out-ch
// thread tile = 8 px (same row, x = pcol0 + 4i) x 8 out-ch (o-pairs packed)
__global__ __launch_bounds__(128) void k_adder(int stage,
                                               const float* __restrict__ w) {
    __shared__ unsigned long long As[CCHUNK * 6 * PSTR];  // splat input, 13.8 KB
    __shared__ unsigned long long Bs[KBLK * 32];          // -w o-pairs,  18.4 KB

    const float* apad = stage ? g_a2 : g_a1;
    float*       part = stage ? g_p2 : g_p1;

    int tid  = threadIdx.x;
    int bx   = blockIdx.x;           // 0..31
    int sp   = blockIdx.y;           // 0..7 (k-split)
    int b    = bx >> 3;
    int row0 = (bx & 7) * 4;         // output rows row0..row0+3
    int c0   = sp * CCHUNK;

    int og    = tid >> 4;            // 0..7  -> out channels og*8..og*8+7
    int pg    = tid & 15;
    int prow  = pg >> 2;             // 0..3
    int pcol0 = pg & 3;              // 0..3

    // stage A: 8 channels x 6 padded rows x 36 cols, value splat into both halves
    const float* ap = apad + (b * C_ + c0) * PLANE;
    for (int i = tid; i < CCHUNK * 6 * PSTR; i += 128) {
        int cc  = i / (6 * PSTR);
        int rem = i - cc * (6 * PSTR);
        int r   = rem / PSTR;
        int q   = rem - r * PSTR;
        unsigned int bits = __float_as_uint(ap[cc * PLANE + (row0 + r) * PSTR + q]);
        As[i] = ((unsigned long long)bits << 32) | bits;
    }
    // stage B: negated weights, o-pairs packed: Bs[k][j] = (-w[2j][k], -w[2j+1][k])
    float* Bsf = (float*)Bs;
    for (int i = tid; i < KBLK * 64; i += 128) {
        int k  = i >> 6;
        int o  = i & 63;
        int cc = k / 9;
        int t9 = k - cc * 9;                 // kh*3+kw
        Bsf[k * 64 + o] = -w[(o * C_ + c0 + cc) * 9 + t9];
    }
    __syncthreads();

    unsigned long long acc[8][4];
#pragma unroll
    for (int i = 0; i < 8; i++)
#pragma unroll
        for (int j = 0; j < 4; j++) acc[i][j] = 0ull;

    const unsigned long long ABSM = 0x7FFFFFFF7FFFFFFFULL;

#pragma unroll 1
    for (int cc = 0; cc < CCHUNK; ++cc) {
#pragma unroll
        for (int kh = 0; kh < 3; ++kh) {
            const unsigned long long* arow =
                &As[cc * (6 * PSTR) + (prow + kh) * PSTR + pcol0];
#pragma unroll
            for (int kw = 0; kw < 3; ++kw) {
                unsigned long long av[8];
#pragma unroll
                for (int i = 0; i < 8; i++) av[i] = arow[4 * i + kw];
                const unsigned long long* brow =
                    &Bs[(cc * 9 + kh * 3 + kw) * 32 + og * 4];
                unsigned long long bv[4];
#pragma unroll
                for (int j = 0; j < 4; j++) bv[j] = brow[j];
#pragma unroll
                for (int i = 0; i < 8; i++) {
#pragma unroll
                    for (int j = 0; j < 4; j++) {
                        unsigned long long d = f2add(av[i], bv[j]) & ABSM; // |a-w|
                        acc[i][j] = f2add(acc[i][j], d);
                    }
                }
            }
        }
    }

    int y = row0 + prow;
    float* pbase = part + ((sp * B_ + b) * C_ + og * 8) * NPIX + y * 32;
#pragma unroll
    for (int j = 0; j < 4; j++) {
#pragma unroll
        for (int i = 0; i < 8; i++) {
            int x = pcol0 + 4 * i;
            unsigned long long a = acc[i][j];
            pbase[(2 * j) * NPIX + x]     = -__uint_as_float((unsigned int)a);
            pbase[(2 * j + 1) * NPIX + x] = -__uint_as_float((unsigned int)(a >> 32));
        }
    }
}

// ---------------- combine adder2 partials + channel means ----------------
__global__ void k_comb_se() {
    int bc  = blockIdx.x;   // 0..255 = b*64 + c
    int tid = threadIdx.x;  // 256
    float lsum = 0.f;
    int base = bc * NPIX;
    for (int p = tid; p < NPIX; p += 256) {
        float v = 0.f;
#pragma unroll
        for (int sp = 0; sp < S_; sp++)
            v += g_p2[sp * (B_ * C_ * NPIX) + base + p];
        g_out2[base + p] = v;
        lsum += v;
    }
#pragma unroll
    for (int off = 16; off; off >>= 1)
        lsum += __shfl_xor_sync(0xffffffffu, lsum, off);
    __shared__ float ws[8];
    if ((tid & 31) == 0) ws[tid >> 5] = lsum;
    __syncthreads();
    if (tid == 0) {
        float t = 0.f;
#pragma unroll
        for (int i = 0; i < 8; i++) t += ws[i];
        g_s[bc] = t * (1.f / 1024.f);
    }
}

// ---------------- SE gate: fc1 -> relu -> fc2 -> sigmoid ----------------
__global__ void k_gate(const float* __restrict__ f1w, const float* __restrict__ f1b,
                       const float* __restrict__ f2w, const float* __restrict__ f2b) {
    __shared__ float sh[256];
    __shared__ float hh[16];
    int tid = threadIdx.x;
    sh[tid] = g_s[tid];
    __syncthreads();
    if (tid < 16) {
        int b = tid >> 2, j = tid & 3;
        float acc = f1b[j];
        for (int c = 0; c < 64; c++) acc += sh[b * 64 + c] * f1w[j * 64 + c];
        hh[tid] = fmaxf(acc, 0.f);
    }
    __syncthreads();
    int b = tid >> 6, c = tid & 63;
    float z = f2b[c];
#pragma unroll
    for (int j = 0; j < 4; j++) z += hh[b * 4 + j] * f2w[c * 4 + j];
    g_g[tid] = 1.f / (1.f + expf(-z));
}

// ---------------- final: out = out2 * g + shortcut(x) ----------------
__global__ void k_final(const float* __restrict__ x, float* __restrict__ out) {
    int idx = blockIdx.x * blockDim.x + threadIdx.x;
    if (idx >= B_ * C_ * NPIX) return;
    out[idx] = g_out2[idx] * g_g[idx >> 10] + x[idx];
}

extern "C" void kernel_launch(void* const* d_in, const int* in_sizes, int n_in,
                              void* d_out, int out_size) {
    const float* x     = (const float*)d_in[0];
    const float* bn1_g = (const float*)d_in[1];
    const float* bn1_b = (const float*)d_in[2];
    const float* bn1_m = (const float*)d_in[3];
    const float* bn1_v = (const float*)d_in[4];
    const float* w1    = (const float*)d_in[5];
    const float* bn2_g = (const float*)d_in[6];
    const float* bn2_b = (const float*)d_in[7];
    const float* bn2_m = (const float*)d_in[8];
    const float* bn2_v = (const float*)d_in[9];
    const float* w2    = (const float*)d_in[10];
    const float* fc1_w = (const float*)d_in[11];
    const float* fc1_b = (const float*)d_in[12];
    const float* fc2_w = (const float*)d_in[13];
    const float* fc2_b = (const float*)d_in[14];
    float* out = (float*)d_out;

    const int padtot = B_ * C_ * PLANE;
    dim3 ag(32, 8);

    k_bnpad<<<(padtot + 255) / 256, 256>>>(x, 0, bn1_g, bn1_b, bn1_m, bn1_v);
    k_adder<<<ag, 128>>>(0, w1);
    k_bnpad<<<(padtot + 255) / 256, 256>>>(nullptr, 1, bn2_g, bn2_b, bn2_m, bn2_v);
    k_adder<<<ag, 128>>>(1, w2);
    k_comb_se<<<256, 256>>>();
    k_gate<<<1, 256>>>(fc1_w, fc1_b, fc2_w, fc2_b);
    k_final<<<(B_ * C_ * NPIX + 255) / 256, 256>>>(x, out);
}